// round 2
// baseline (speedup 1.0000x reference)
#include <cuda_runtime.h>
#include <cstdint>
#include <cstddef>

#define T_STEPS 2048
#define H_DIM   512
#define B_DIM   32
#define D_IN    128
#define ALPHA   0.1f

// ---------------------------------------------------------------------------
// Kernel 1: x_proj GEMM.  C[M,N] = A[M,K] * B[N,K]^T
//   A = x [65536,128], B = I [512,128], C = out [65536,512]
// BM=BN=128, BK=8, 256 threads, 8x8 microtile -> FFMA-bound.
// ---------------------------------------------------------------------------
__global__ __launch_bounds__(256) void xproj_gemm(const float* __restrict__ A,
                                                  const float* __restrict__ B,
                                                  float* __restrict__ C) {
    __shared__ float As[8][128];
    __shared__ float Bs[8][128];

    const int tid = threadIdx.x;
    const int bm  = blockIdx.x * 128;
    const int bn  = blockIdx.y * 128;

    // loaders: each thread loads one float4 (along K) per operand per tile
    const int lr = tid >> 1;          // row 0..127
    const int lc = (tid & 1) * 4;     // k offset 0 or 4
    const float* Ap = A + (size_t)(bm + lr) * D_IN + lc;
    const float* Bp = B + (size_t)(bn + lr) * D_IN + lc;

    // compute mapping: 16x16 thread grid, 8x8 outputs each
    const int tx = (tid & 15) * 8;
    const int ty = (tid >> 4) * 8;

    float acc[8][8] = {};

    for (int k0 = 0; k0 < D_IN; k0 += 8) {
        const float4 av = *(const float4*)(Ap + k0);
        const float4 bv = *(const float4*)(Bp + k0);
        __syncthreads();  // protect previous iteration's reads
        As[lc + 0][lr] = av.x; As[lc + 1][lr] = av.y;
        As[lc + 2][lr] = av.z; As[lc + 3][lr] = av.w;
        Bs[lc + 0][lr] = bv.x; Bs[lc + 1][lr] = bv.y;
        Bs[lc + 2][lr] = bv.z; Bs[lc + 3][lr] = bv.w;
        __syncthreads();

        #pragma unroll
        for (int k = 0; k < 8; k++) {
            float a[8], bb[8];
            *(float4*)&a[0]  = *(const float4*)&As[k][ty];
            *(float4*)&a[4]  = *(const float4*)&As[k][ty + 4];
            *(float4*)&bb[0] = *(const float4*)&Bs[k][tx];
            *(float4*)&bb[4] = *(const float4*)&Bs[k][tx + 4];
            #pragma unroll
            for (int i = 0; i < 8; i++)
                #pragma unroll
                for (int j = 0; j < 8; j++)
                    acc[i][j] = fmaf(a[i], bb[j], acc[i][j]);
        }
    }

    #pragma unroll
    for (int i = 0; i < 8; i++) {
        float* Cp = C + (size_t)(bm + ty + i) * H_DIM + bn + tx;
        *(float4*)(Cp)     = make_float4(acc[i][0], acc[i][1], acc[i][2], acc[i][3]);
        *(float4*)(Cp + 4) = make_float4(acc[i][4], acc[i][5], acc[i][6], acc[i][7]);
    }
}

// ---------------------------------------------------------------------------
// Kernel 2: the sequential scan. ONE WARP per batch, 16 h per thread.
// Cross-thread state per step is only (s0,s1): pure in-warp shuffle reduce —
// no __syncthreads, no shared memory on the chain.
//
// Layout: thread `lane` owns h = g*128 + lane*4 + k  (g=0..3, k=0..3)
//   -> 4x LDG.128 / 4x STG.128 per step, fully coalesced.
// out initially holds x_proj; overwritten in place (prefetch reads t+2
// strictly before that location is written at iteration t+2).
// ---------------------------------------------------------------------------
__global__ __launch_bounds__(32) void rnn_scan(const float* __restrict__ m,
                                               const float* __restrict__ n,
                                               float* __restrict__ out) {
    const int b    = blockIdx.x;
    const int lane = threadIdx.x;
    const float OMA = 1.0f - ALPHA;

    // per-h constants
    float n0[16], n1[16], am0[16], am1[16];
    #pragma unroll
    for (int g = 0; g < 4; g++) {
        const int h0 = g * 128 + lane * 4;
        #pragma unroll
        for (int k = 0; k < 4; k++) {
            const int i = g * 4 + k;
            n0[i]  = n[2 * (h0 + k) + 0];
            n1[i]  = n[2 * (h0 + k) + 1];
            am0[i] = ALPHA * m[2 * (h0 + k) + 0];
            am1[i] = ALPHA * m[2 * (h0 + k) + 1];
        }
    }

    float* base = out + (size_t)b * T_STEPS * H_DIM + lane * 4;

    float hs[16];
    #pragma unroll
    for (int i = 0; i < 16; i++) hs[i] = 0.0f;

    // depth-2 prefetch of x_proj rows
    float4 xp[2][4];
    #pragma unroll
    for (int d = 0; d < 2; d++)
        #pragma unroll
        for (int g = 0; g < 4; g++)
            xp[d][g] = *(const float4*)(base + (size_t)d * H_DIM + g * 128);

    #pragma unroll 1
    for (int t = 0; t < T_STEPS; t++) {
        const int cur = t & 1;

        // tanh of current state
        float th[16];
        #pragma unroll
        for (int i = 0; i < 16; i++)
            asm("tanh.approx.f32 %0, %1;" : "=f"(th[i]) : "f"(hs[i]));

        // rank-2 products, 4 independent accumulator chains per component
        float q0[4], q1[4];
        #pragma unroll
        for (int g = 0; g < 4; g++) {
            q0[g] = th[g * 4] * n0[g * 4];
            q1[g] = th[g * 4] * n1[g * 4];
            #pragma unroll
            for (int k = 1; k < 4; k++) {
                const int i = g * 4 + k;
                q0[g] = fmaf(th[i], n0[i], q0[g]);
                q1[g] = fmaf(th[i], n1[i], q1[g]);
            }
        }
        float p0 = (q0[0] + q0[1]) + (q0[2] + q0[3]);
        float p1 = (q1[0] + q1[1]) + (q1[2] + q1[3]);

        // v = OMA*h + ALPHA*xp  — independent of the reduction, overlaps it
        float v[16];
        #pragma unroll
        for (int g = 0; g < 4; g++) {
            const float4 x4 = xp[cur][g];
            const float xe[4] = {x4.x, x4.y, x4.z, x4.w};
            #pragma unroll
            for (int k = 0; k < 4; k++) {
                const int i = g * 4 + k;
                v[i] = fmaf(ALPHA, xe[k], OMA * hs[i]);
            }
        }

        // full-warp butterfly reduction -> every lane holds (s0, s1)
        #pragma unroll
        for (int o = 16; o; o >>= 1) {
            p0 += __shfl_xor_sync(0xffffffffu, p0, o);
            p1 += __shfl_xor_sync(0xffffffffu, p1, o);
        }

        // prefetch t+2 while the update retires
        if (t + 2 < T_STEPS) {
            #pragma unroll
            for (int g = 0; g < 4; g++)
                xp[cur][g] = *(const float4*)(base + (size_t)(t + 2) * H_DIM + g * 128);
        }

        // state update + store
        #pragma unroll
        for (int g = 0; g < 4; g++) {
            float4 o4;
            float* oe = (float*)&o4;
            #pragma unroll
            for (int k = 0; k < 4; k++) {
                const int i = g * 4 + k;
                hs[i] = fmaf(am0[i], p0, fmaf(am1[i], p1, v[i]));
                oe[k] = hs[i];
            }
            *(float4*)(base + (size_t)t * H_DIM + g * 128) = o4;
        }
    }
}

// ---------------------------------------------------------------------------
extern "C" void kernel_launch(void* const* d_in, const int* in_sizes, int n_in,
                              void* d_out, int out_size) {
    const float* x = (const float*)d_in[0];   // [32, 2048, 128]
    const float* m = (const float*)d_in[1];   // [512, 2]
    const float* n = (const float*)d_in[2];   // [512, 2]
    const float* I = (const float*)d_in[3];   // [512, 128]
    float* out = (float*)d_out;               // [32, 2048, 512]

    (void)in_sizes; (void)n_in; (void)out_size;

    dim3 ggrid((B_DIM * T_STEPS) / 128, H_DIM / 128);
    xproj_gemm<<<ggrid, 256>>>(x, I, out);
    rnn_scan<<<B_DIM, 32>>>(m, n, out);
}

// round 3
// speedup vs baseline: 2.4520x; 2.4520x over previous
#include <cuda_runtime.h>
#include <cstdint>
#include <cstddef>

#define T_STEPS 2048
#define H_DIM   512
#define B_DIM   32
#define D_IN    128
#define ALPHA   0.1f

// ---------------------------------------------------------------------------
// Kernel 1: x_proj GEMM.  C[M,N] = A[M,K] * B[N,K]^T
//   A = x [65536,128], B = I [512,128], C = out [65536,512]
// BM=BN=128, BK=8, 256 threads, 8x8 microtile -> FFMA-bound.
// ---------------------------------------------------------------------------
__global__ __launch_bounds__(256) void xproj_gemm(const float* __restrict__ A,
                                                  const float* __restrict__ B,
                                                  float* __restrict__ C) {
    __shared__ float As[8][128];
    __shared__ float Bs[8][128];

    const int tid = threadIdx.x;
    const int bm  = blockIdx.x * 128;
    const int bn  = blockIdx.y * 128;

    const int lr = tid >> 1;          // row 0..127
    const int lc = (tid & 1) * 4;     // k offset 0 or 4
    const float* Ap = A + (size_t)(bm + lr) * D_IN + lc;
    const float* Bp = B + (size_t)(bn + lr) * D_IN + lc;

    const int tx = (tid & 15) * 8;
    const int ty = (tid >> 4) * 8;

    float acc[8][8] = {};

    for (int k0 = 0; k0 < D_IN; k0 += 8) {
        const float4 av = *(const float4*)(Ap + k0);
        const float4 bv = *(const float4*)(Bp + k0);
        __syncthreads();  // protect previous iteration's reads
        As[lc + 0][lr] = av.x; As[lc + 1][lr] = av.y;
        As[lc + 2][lr] = av.z; As[lc + 3][lr] = av.w;
        Bs[lc + 0][lr] = bv.x; Bs[lc + 1][lr] = bv.y;
        Bs[lc + 2][lr] = bv.z; Bs[lc + 3][lr] = bv.w;
        __syncthreads();

        #pragma unroll
        for (int k = 0; k < 8; k++) {
            float a[8], bb[8];
            *(float4*)&a[0]  = *(const float4*)&As[k][ty];
            *(float4*)&a[4]  = *(const float4*)&As[k][ty + 4];
            *(float4*)&bb[0] = *(const float4*)&Bs[k][tx];
            *(float4*)&bb[4] = *(const float4*)&Bs[k][tx + 4];
            #pragma unroll
            for (int i = 0; i < 8; i++)
                #pragma unroll
                for (int j = 0; j < 8; j++)
                    acc[i][j] = fmaf(a[i], bb[j], acc[i][j]);
        }
    }

    #pragma unroll
    for (int i = 0; i < 8; i++) {
        float* Cp = C + (size_t)(bm + ty + i) * H_DIM + bn + tx;
        *(float4*)(Cp)     = make_float4(acc[i][0], acc[i][1], acc[i][2], acc[i][3]);
        *(float4*)(Cp + 4) = make_float4(acc[i][4], acc[i][5], acc[i][6], acc[i][7]);
    }
}

// ---------------------------------------------------------------------------
// packed fp32x2 add (Blackwell FADD2 path)
// ---------------------------------------------------------------------------
__device__ __forceinline__ unsigned long long f2add(unsigned long long a,
                                                    unsigned long long b) {
    unsigned long long r;
    asm("add.rn.f32x2 %0, %1, %2;" : "=l"(r) : "l"(a), "l"(b));
    return r;
}

// ---------------------------------------------------------------------------
// Kernel 2: sequential scan. 4 warps (128 threads) per batch, 4 h per thread
// (thread tid owns h = tid*4 .. tid*4+3 -> coalesced float4 ld/st).
//
// Per step:
//   tanh -> rank-2 partial products -> 3-level butterfly (lanes 0-3 hold
//   coset partials) -> smem exchange (16 float2) -> one __syncthreads
//   (defer-blocking) -> packed f32x2 gather tree -> update.
// out initially holds x_proj; overwritten in place (each address touched by
// exactly one thread; prefetch of row t+4 precedes its write in program order).
// ---------------------------------------------------------------------------
__global__ __launch_bounds__(128) void rnn_scan(const float* __restrict__ m,
                                                const float* __restrict__ n,
                                                float* __restrict__ out) {
    const int b    = blockIdx.x;
    const int tid  = threadIdx.x;
    const int lane = tid & 31;
    const int wid  = tid >> 5;
    const float OMA = 1.0f - ALPHA;

    __shared__ __align__(16) float2 part[2][16];   // [parity][warp*4 + coset]

    // per-h constants (h = tid*4 + k)
    float n0[4], n1[4], am0[4], am1[4];
    {
        const float4 na = *(const float4*)(n + 8 * tid);
        const float4 nb = *(const float4*)(n + 8 * tid + 4);
        n0[0] = na.x; n1[0] = na.y; n0[1] = na.z; n1[1] = na.w;
        n0[2] = nb.x; n1[2] = nb.y; n0[3] = nb.z; n1[3] = nb.w;
        const float4 ma = *(const float4*)(m + 8 * tid);
        const float4 mb = *(const float4*)(m + 8 * tid + 4);
        am0[0] = ALPHA * ma.x; am1[0] = ALPHA * ma.y;
        am0[1] = ALPHA * ma.z; am1[1] = ALPHA * ma.w;
        am0[2] = ALPHA * mb.x; am1[2] = ALPHA * mb.y;
        am0[3] = ALPHA * mb.z; am1[3] = ALPHA * mb.w;
    }

    float* base = out + (size_t)b * T_STEPS * H_DIM + tid * 4;

    float hs[4] = {0.0f, 0.0f, 0.0f, 0.0f};

    // depth-4 prefetch of x_proj rows
    float4 xp[4];
    #pragma unroll
    for (int d = 0; d < 4; d++) xp[d] = *(const float4*)(base + (size_t)d * H_DIM);

    #pragma unroll 1
    for (int t = 0; t < T_STEPS; t += 4) {
        #pragma unroll
        for (int u = 0; u < 4; u++) {
            const int tt = t + u;
            const float4 x4 = xp[u];

            float th[4];
            #pragma unroll
            for (int k = 0; k < 4; k++)
                asm("tanh.approx.f32 %0, %1;" : "=f"(th[k]) : "f"(hs[k]));

            // rank-2 partial products (depth-3 FMA)
            float p0 = fmaf(th[1], n0[1], th[0] * n0[0]) +
                       fmaf(th[3], n0[3], th[2] * n0[2]);
            float p1 = fmaf(th[1], n1[1], th[0] * n1[0]) +
                       fmaf(th[3], n1[3], th[2] * n1[2]);

            // v = OMA*h + ALPHA*xp  (independent of reduction; overlaps it)
            float v[4];
            v[0] = fmaf(ALPHA, x4.x, OMA * hs[0]);
            v[1] = fmaf(ALPHA, x4.y, OMA * hs[1]);
            v[2] = fmaf(ALPHA, x4.z, OMA * hs[2]);
            v[3] = fmaf(ALPHA, x4.w, OMA * hs[3]);

            // 3-level butterfly: lane l ends with sum over {l' : l'&3 == l&3}
            #pragma unroll
            for (int o = 16; o >= 4; o >>= 1) {
                p0 += __shfl_xor_sync(0xffffffffu, p0, o);
                p1 += __shfl_xor_sync(0xffffffffu, p1, o);
            }

            const int par = tt & 1;
            if (lane < 4) part[par][wid * 4 + lane] = make_float2(p0, p1);
            __syncthreads();   // defer-blocking: stalls only at the LDS below

            // prefetch row tt+4 (independent; overlaps barrier/LDS wait)
            if (tt + 4 < T_STEPS)
                xp[u] = *(const float4*)(base + (size_t)(tt + 4) * H_DIM);

            // gather 16 float2 partials with packed f32x2 adds (depth-4 tree)
            const ulonglong2* pp = (const ulonglong2*)&part[par][0];
            unsigned long long r[8];
            #pragma unroll
            for (int w = 0; w < 8; w++) {
                const ulonglong2 q = pp[w];
                r[w] = f2add(q.x, q.y);
            }
            r[0] = f2add(r[0], r[1]); r[2] = f2add(r[2], r[3]);
            r[4] = f2add(r[4], r[5]); r[6] = f2add(r[6], r[7]);
            r[0] = f2add(r[0], r[2]); r[4] = f2add(r[4], r[6]);
            r[0] = f2add(r[0], r[4]);

            float s0, s1;
            asm("mov.b64 {%0, %1}, %2;" : "=f"(s0), "=f"(s1) : "l"(r[0]));

            // state update + store
            float4 o4;
            hs[0] = fmaf(am0[0], s0, fmaf(am1[0], s1, v[0])); o4.x = hs[0];
            hs[1] = fmaf(am0[1], s0, fmaf(am1[1], s1, v[1])); o4.y = hs[1];
            hs[2] = fmaf(am0[2], s0, fmaf(am1[2], s1, v[2])); o4.z = hs[2];
            hs[3] = fmaf(am0[3], s0, fmaf(am1[3], s1, v[3])); o4.w = hs[3];
            *(float4*)(base + (size_t)tt * H_DIM) = o4;
        }
    }
}

// ---------------------------------------------------------------------------
extern "C" void kernel_launch(void* const* d_in, const int* in_sizes, int n_in,
                              void* d_out, int out_size) {
    const float* x = (const float*)d_in[0];   // [32, 2048, 128]
    const float* m = (const float*)d_in[1];   // [512, 2]
    const float* n = (const float*)d_in[2];   // [512, 2]
    const float* I = (const float*)d_in[3];   // [512, 128]
    float* out = (float*)d_out;               // [32, 2048, 512]

    (void)in_sizes; (void)n_in; (void)out_size;

    dim3 ggrid((B_DIM * T_STEPS) / 128, H_DIM / 128);
    xproj_gemm<<<ggrid, 256>>>(x, I, out);
    rnn_scan<<<B_DIM, 128>>>(m, n, out);
}